// round 6
// baseline (speedup 1.0000x reference)
#include <cuda_runtime.h>

// Fixed shape: [B=2, D=128, H=160, W=192, C=3] float32 fields.
#define DD 128
#define HH 160
#define WW 192
#define NB 2
#define DHW (DD * HH * WW)          // 3,932,160 voxels per batch
#define TOTAL (NB * DHW)            // 7,864,320 voxels
#define QSCALE 1024.0f
#define QINV   (1.0f / 1024.0f)

// Z-paired quantized gather volumes: per voxel a 16B record holding int16
// fixed-point values of this voxel AND its z+1 neighbor (clamped at row end).
//   U.x = pk(lo.x, lo.y)  U.y = pk(lo.z, hi.x)  U.z = pk(hi.y, hi.z)  U.w = 0
__device__ uint4 g_t1p[TOTAL];
__device__ uint4 g_t2p[TOTAL];

struct f3 { float x, y, z; };

__device__ __forceinline__ unsigned pk(float lo, float hi) {
    int il = __float2int_rn(lo * QSCALE);
    int ih = __float2int_rn(hi * QSCALE);
    return (unsigned)(il & 0xFFFF) | ((unsigned)ih << 16);
}
__device__ __forceinline__ float sxlo(unsigned u) {
    return (float)((int)(u << 16) >> 16);
}
__device__ __forceinline__ float sxhi(unsigned u) {
    return (float)((int)u >> 16);
}

// ---------------------------------------------------------------------------
// Merged quant for t1+t2 (grid.y selects tensor). Each thread packs 4 voxels;
// records staged in smem and written warp-coalesced (1024 uint4 per block).
// ---------------------------------------------------------------------------
__global__ __launch_bounds__(256)
void pairquant2_kernel(const float4* __restrict__ t1,
                       const float4* __restrict__ t2,
                       uint4* __restrict__ d1,
                       uint4* __restrict__ d2) {
    __shared__ uint4 st[1024];

    const float4* __restrict__ src = blockIdx.y ? t2 : t1;
    uint4* __restrict__ dst = blockIdx.y ? d2 : d1;

    int g = blockIdx.x * 256 + threadIdx.x;        // voxel-group of 4

    float4 a = __ldg(src + g * 3 + 0);   // v0.xyz v1.x
    float4 b = __ldg(src + g * 3 + 1);   // v1.yz  v2.xy
    float4 c = __ldg(src + g * 3 + 2);   // v2.z   v3.xyz

    int w0 = (g % (WW / 4)) * 4;         // w coord of first voxel in group
    float nx, ny, nz;                    // voxel v4 (w0+4) or clamp to v3
    if (w0 + 4 < WW) {
        float4 d = __ldg(src + g * 3 + 3);
        nx = d.x; ny = d.y; nz = d.z;
    } else {
        nx = c.y; ny = c.z; nz = c.w;
    }

    float vx[5] = {a.x, a.w, b.z, c.y, nx};
    float vy[5] = {a.y, b.x, b.w, c.z, ny};
    float vz[5] = {a.z, b.y, c.x, c.w, nz};

#pragma unroll
    for (int i = 0; i < 4; i++) {
        uint4 u;
        u.x = pk(vx[i], vy[i]);
        u.y = pk(vz[i], vx[i + 1]);
        u.z = pk(vy[i + 1], vz[i + 1]);
        u.w = 0u;
        st[threadIdx.x * 4 + i] = u;
    }
    __syncthreads();

    size_t out_base = (size_t)blockIdx.x * 1024;
#pragma unroll
    for (int i = 0; i < 4; i++) {
        int k = threadIdx.x + i * 256;
        dst[out_base + k] = st[k];
    }
}

// ---------------------------------------------------------------------------
// Gather the 4 z-paired records for one trilerp (batched so ptxas can issue
// all loads back-to-back), then reduce.
// ---------------------------------------------------------------------------
struct Coord {
    int r00, r01, r10, r11;     // record indices
    float w00, w01, w10, w11;   // xy weights
    float wz0q, wz1q;           // z weights with dequant folded in
};

__device__ __forceinline__ Coord make_coord(float fx, float fy, float fz) {
    fx = fminf(fmaxf(fx, 0.f), (float)(DD - 1));
    fy = fminf(fmaxf(fy, 0.f), (float)(HH - 1));
    fz = fminf(fmaxf(fz, 0.f), (float)(WW - 1));
    float x0f = floorf(fx), y0f = floorf(fy), z0f = floorf(fz);
    int x0 = (int)x0f, y0 = (int)y0f, z0 = (int)z0f;
    int x1 = min(x0 + 1, DD - 1);
    int y1 = min(y0 + 1, HH - 1);
    float wx1 = fx - x0f, wy1 = fy - y0f, wz1 = fz - z0f;
    float wx0 = 1.f - wx1, wy0 = 1.f - wy1, wz0 = 1.f - wz1;
    Coord c;
    c.r00 = (x0 * HH + y0) * WW + z0;
    c.r01 = (x0 * HH + y1) * WW + z0;
    c.r10 = (x1 * HH + y0) * WW + z0;
    c.r11 = (x1 * HH + y1) * WW + z0;
    c.w00 = wx0 * wy0; c.w01 = wx0 * wy1;
    c.w10 = wx1 * wy0; c.w11 = wx1 * wy1;
    c.wz0q = wz0 * QINV; c.wz1q = wz1 * QINV;
    return c;
}

__device__ __forceinline__ f3 reduce_trilerp(const Coord& c,
                                             uint4 u00, uint4 u01,
                                             uint4 u10, uint4 u11) {
    f3 r;
    r.x = c.w00 * fmaf(c.wz0q, sxlo(u00.x), c.wz1q * sxhi(u00.y))
        + c.w01 * fmaf(c.wz0q, sxlo(u01.x), c.wz1q * sxhi(u01.y))
        + c.w10 * fmaf(c.wz0q, sxlo(u10.x), c.wz1q * sxhi(u10.y))
        + c.w11 * fmaf(c.wz0q, sxlo(u11.x), c.wz1q * sxhi(u11.y));
    r.y = c.w00 * fmaf(c.wz0q, sxhi(u00.x), c.wz1q * sxlo(u00.z))
        + c.w01 * fmaf(c.wz0q, sxhi(u01.x), c.wz1q * sxlo(u01.z))
        + c.w10 * fmaf(c.wz0q, sxhi(u10.x), c.wz1q * sxlo(u10.z))
        + c.w11 * fmaf(c.wz0q, sxhi(u11.x), c.wz1q * sxlo(u11.z));
    r.z = c.w00 * fmaf(c.wz0q, sxlo(u00.y), c.wz1q * sxhi(u00.z))
        + c.w01 * fmaf(c.wz0q, sxlo(u01.y), c.wz1q * sxhi(u01.z))
        + c.w10 * fmaf(c.wz0q, sxlo(u10.y), c.wz1q * sxhi(u10.z))
        + c.w11 * fmaf(c.wz0q, sxlo(u11.y), c.wz1q * sxhi(u11.z));
    return r;
}

// ---------------------------------------------------------------------------
// Fused compose, 2 voxels per thread (512 voxels per block).
// Both voxels' gathers for each phase are issued together (MLP=8).
// ---------------------------------------------------------------------------
__global__ __launch_bounds__(256)
void compose2_kernel(const float4* __restrict__ t3v,
                     const uint4* __restrict__ t1p,
                     const uint4* __restrict__ t2p,
                     float4* __restrict__ outv) {
    __shared__ float s_in[1536];    // 512 voxels * 3ch
    __shared__ float s_out[1536];

    int tx = threadIdx.x;
    {   // stage t3 for 512 voxels: 384 float4
        const float4* src = t3v + (size_t)blockIdx.x * 384;
        ((float4*)s_in)[tx] = __ldg(src + tx);
        if (tx < 128) ((float4*)s_in)[256 + tx] = __ldg(src + 256 + tx);
    }
    __syncthreads();

    int vox0 = blockIdx.x * 512 + tx * 2;
    int vox1 = vox0 + 1;

    // per-voxel coords
    int w0 = vox0 % WW;  int t0 = vox0 / WW;  int h0 = t0 % HH;  t0 /= HH;
    int d0 = t0 % DD;    int b0 = t0 / DD;
    int w1 = vox1 % WW;  int t1i = vox1 / WW; int h1 = t1i % HH; t1i /= HH;
    int d1 = t1i % DD;   int b1 = t1i / DD;

    const uint4* v2a = t2p + (size_t)b0 * DHW;
    const uint4* v2b = t2p + (size_t)b1 * DHW;
    const uint4* v1a = t1p + (size_t)b0 * DHW;
    const uint4* v1b = t1p + (size_t)b1 * DHW;

    float sx0 = s_in[tx * 6 + 0], sy0 = s_in[tx * 6 + 1], sz0 = s_in[tx * 6 + 2];
    float sx1 = s_in[tx * 6 + 3], sy1 = s_in[tx * 6 + 4], sz1 = s_in[tx * 6 + 5];

    // ---- phase 1: gather t2 for both voxels (8 independent LDG.128) ----
    Coord ca = make_coord((float)d0 + sx0, (float)h0 + sy0, (float)w0 + sz0);
    Coord cb = make_coord((float)d1 + sx1, (float)h1 + sy1, (float)w1 + sz1);

    uint4 a00 = __ldg(v2a + ca.r00), a01 = __ldg(v2a + ca.r01);
    uint4 a10 = __ldg(v2a + ca.r10), a11 = __ldg(v2a + ca.r11);
    uint4 b00 = __ldg(v2b + cb.r00), b01 = __ldg(v2b + cb.r01);
    uint4 b10 = __ldg(v2b + cb.r10), b11 = __ldg(v2b + cb.r11);

    f3 g2a = reduce_trilerp(ca, a00, a01, a10, a11);
    f3 g2b = reduce_trilerp(cb, b00, b01, b10, b11);

    float cx0 = sx0 + g2a.x, cy0 = sy0 + g2a.y, cz0 = sz0 + g2a.z;
    float cx1 = sx1 + g2b.x, cy1 = sy1 + g2b.y, cz1 = sz1 + g2b.z;

    // ---- phase 2: gather t1 for both voxels ----
    Coord da = make_coord((float)d0 + cx0, (float)h0 + cy0, (float)w0 + cz0);
    Coord db = make_coord((float)d1 + cx1, (float)h1 + cy1, (float)w1 + cz1);

    uint4 c00 = __ldg(v1a + da.r00), c01 = __ldg(v1a + da.r01);
    uint4 c10 = __ldg(v1a + da.r10), c11 = __ldg(v1a + da.r11);
    uint4 d00 = __ldg(v1b + db.r00), d01 = __ldg(v1b + db.r01);
    uint4 d10 = __ldg(v1b + db.r10), d11 = __ldg(v1b + db.r11);

    f3 g1a = reduce_trilerp(da, c00, c01, c10, c11);
    f3 g1b = reduce_trilerp(db, d00, d01, d10, d11);

    s_out[tx * 6 + 0] = cx0 + g1a.x;
    s_out[tx * 6 + 1] = cy0 + g1a.y;
    s_out[tx * 6 + 2] = cz0 + g1a.z;
    s_out[tx * 6 + 3] = cx1 + g1b.x;
    s_out[tx * 6 + 4] = cy1 + g1b.y;
    s_out[tx * 6 + 5] = cz1 + g1b.z;
    __syncthreads();

    {   // write 384 float4
        float4* dst = outv + (size_t)blockIdx.x * 384;
        dst[tx] = ((float4*)s_out)[tx];
        if (tx < 128) dst[256 + tx] = ((float4*)s_out)[256 + tx];
    }
}

extern "C" void kernel_launch(void* const* d_in, const int* in_sizes, int n_in,
                              void* d_out, int out_size) {
    const float* t1 = (const float*)d_in[0];
    const float* t2 = (const float*)d_in[1];
    const float* t3 = (const float*)d_in[2];
    float* out = (float*)d_out;

    uint4 *t1p, *t2p;
    cudaGetSymbolAddress((void**)&t1p, g_t1p);
    cudaGetSymbolAddress((void**)&t2p, g_t2p);

    dim3 qgrid(TOTAL / 1024, 2);
    pairquant2_kernel<<<qgrid, 256>>>((const float4*)t1, (const float4*)t2,
                                      t1p, t2p);

    int blocks = TOTAL / 512;     // 15360
    compose2_kernel<<<blocks, 256>>>((const float4*)t3, t1p, t2p, (float4*)out);
}

// round 7
// speedup vs baseline: 1.0261x; 1.0261x over previous
#include <cuda_runtime.h>

// Fixed shape: [B=2, D=128, H=160, W=192, C=3] float32 fields.
#define DD 128
#define HH 160
#define WW 192
#define NB 2
#define DHW (DD * HH * WW)          // 3,932,160 voxels per batch
#define TOTAL (NB * DHW)            // 7,864,320 voxels
#define QSCALE 1024.0f
#define QINV   (1.0f / 1024.0f)

// Z-paired quantized gather volumes: per voxel a 16B record holding int16
// fixed-point values of this voxel AND its z+1 neighbor (clamped at row end).
//   U.x = pk(lo.x, lo.y)  U.y = pk(lo.z, hi.x)  U.z = pk(hi.y, hi.z)  U.w = 0
__device__ uint4 g_t1p[TOTAL];
__device__ uint4 g_t2p[TOTAL];

struct f3 { float x, y, z; };

__device__ __forceinline__ unsigned pk(float lo, float hi) {
    int il = __float2int_rn(lo * QSCALE);
    int ih = __float2int_rn(hi * QSCALE);
    return (unsigned)(il & 0xFFFF) | ((unsigned)ih << 16);
}
__device__ __forceinline__ float sxlo(unsigned u) {
    return (float)((int)(u << 16) >> 16);
}
__device__ __forceinline__ float sxhi(unsigned u) {
    return (float)((int)u >> 16);
}

// ---------------------------------------------------------------------------
// Merged quant for t1+t2 (grid.y selects tensor). Each thread packs 4 voxels;
// records staged in smem and written warp-coalesced (1024 uint4 per block).
// ---------------------------------------------------------------------------
__global__ __launch_bounds__(256)
void pairquant2_kernel(const float4* __restrict__ t1,
                       const float4* __restrict__ t2,
                       uint4* __restrict__ d1,
                       uint4* __restrict__ d2) {
    __shared__ uint4 st[1024];

    const float4* __restrict__ src = blockIdx.y ? t2 : t1;
    uint4* __restrict__ dst = blockIdx.y ? d2 : d1;

    int g = blockIdx.x * 256 + threadIdx.x;        // voxel-group of 4

    float4 a = __ldg(src + g * 3 + 0);   // v0.xyz v1.x
    float4 b = __ldg(src + g * 3 + 1);   // v1.yz  v2.xy
    float4 c = __ldg(src + g * 3 + 2);   // v2.z   v3.xyz

    int w0 = (g % (WW / 4)) * 4;         // w coord of first voxel in group
    float nx, ny, nz;                    // voxel v4 (w0+4) or clamp to v3
    if (w0 + 4 < WW) {
        float4 d = __ldg(src + g * 3 + 3);
        nx = d.x; ny = d.y; nz = d.z;
    } else {
        nx = c.y; ny = c.z; nz = c.w;
    }

    float vx[5] = {a.x, a.w, b.z, c.y, nx};
    float vy[5] = {a.y, b.x, b.w, c.z, ny};
    float vz[5] = {a.z, b.y, c.x, c.w, nz};

#pragma unroll
    for (int i = 0; i < 4; i++) {
        uint4 u;
        u.x = pk(vx[i], vy[i]);
        u.y = pk(vz[i], vx[i + 1]);
        u.z = pk(vy[i + 1], vz[i + 1]);
        u.w = 0u;
        st[threadIdx.x * 4 + i] = u;
    }
    __syncthreads();

    size_t out_base = (size_t)blockIdx.x * 1024;
#pragma unroll
    for (int i = 0; i < 4; i++) {
        int k = threadIdx.x + i * 256;
        dst[out_base + k] = st[k];
    }
}

// ---------------------------------------------------------------------------
// Coord/gather helpers for z-paired records.
// ---------------------------------------------------------------------------
struct Coord {
    int r00, r01, r10, r11;     // record indices
    float w00, w01, w10, w11;   // xy weights
    float wz0q, wz1q;           // z weights with dequant folded in
};

__device__ __forceinline__ Coord make_coord(float fx, float fy, float fz) {
    fx = fminf(fmaxf(fx, 0.f), (float)(DD - 1));
    fy = fminf(fmaxf(fy, 0.f), (float)(HH - 1));
    fz = fminf(fmaxf(fz, 0.f), (float)(WW - 1));
    float x0f = floorf(fx), y0f = floorf(fy), z0f = floorf(fz);
    int x0 = (int)x0f, y0 = (int)y0f, z0 = (int)z0f;
    int x1 = min(x0 + 1, DD - 1);
    int y1 = min(y0 + 1, HH - 1);
    float wx1 = fx - x0f, wy1 = fy - y0f, wz1 = fz - z0f;
    float wx0 = 1.f - wx1, wy0 = 1.f - wy1, wz0 = 1.f - wz1;
    Coord c;
    c.r00 = (x0 * HH + y0) * WW + z0;
    c.r01 = (x0 * HH + y1) * WW + z0;
    c.r10 = (x1 * HH + y0) * WW + z0;
    c.r11 = (x1 * HH + y1) * WW + z0;
    c.w00 = wx0 * wy0; c.w01 = wx0 * wy1;
    c.w10 = wx1 * wy0; c.w11 = wx1 * wy1;
    c.wz0q = wz0 * QINV; c.wz1q = wz1 * QINV;
    return c;
}

__device__ __forceinline__ f3 reduce_trilerp(const Coord& c,
                                             uint4 u00, uint4 u01,
                                             uint4 u10, uint4 u11) {
    f3 r;
    r.x = c.w00 * fmaf(c.wz0q, sxlo(u00.x), c.wz1q * sxhi(u00.y))
        + c.w01 * fmaf(c.wz0q, sxlo(u01.x), c.wz1q * sxhi(u01.y))
        + c.w10 * fmaf(c.wz0q, sxlo(u10.x), c.wz1q * sxhi(u10.y))
        + c.w11 * fmaf(c.wz0q, sxlo(u11.x), c.wz1q * sxhi(u11.y));
    r.y = c.w00 * fmaf(c.wz0q, sxhi(u00.x), c.wz1q * sxlo(u00.z))
        + c.w01 * fmaf(c.wz0q, sxhi(u01.x), c.wz1q * sxlo(u01.z))
        + c.w10 * fmaf(c.wz0q, sxhi(u10.x), c.wz1q * sxlo(u10.z))
        + c.w11 * fmaf(c.wz0q, sxhi(u11.x), c.wz1q * sxlo(u11.z));
    r.z = c.w00 * fmaf(c.wz0q, sxlo(u00.y), c.wz1q * sxhi(u00.z))
        + c.w01 * fmaf(c.wz0q, sxlo(u01.y), c.wz1q * sxhi(u01.z))
        + c.w10 * fmaf(c.wz0q, sxlo(u10.y), c.wz1q * sxhi(u10.z))
        + c.w11 * fmaf(c.wz0q, sxlo(u11.y), c.wz1q * sxhi(u11.z));
    return r;
}

// ---------------------------------------------------------------------------
// Fused compose, 2 voxels per thread with BLOCK-STRIDED assignment:
// thread tx handles voxels (base + tx) and (base + 256 + tx), so every gather
// instruction's warp footprint stays 32 contiguous voxels (max line sharing),
// while each thread carries 8 independent LDG.128 per phase (2x MLP).
// Blocks of 512 voxels never straddle a batch (DHW % 512 == 0).
// ---------------------------------------------------------------------------
__global__ __launch_bounds__(256)
void compose2s_kernel(const float4* __restrict__ t3v,
                      const uint4* __restrict__ t1p,
                      const uint4* __restrict__ t2p,
                      float4* __restrict__ outv) {
    __shared__ float s_in[1536];    // 512 voxels * 3ch
    __shared__ float s_out[1536];

    int tx = threadIdx.x;
    {   // stage t3 for 512 voxels: 384 float4
        const float4* src = t3v + (size_t)blockIdx.x * 384;
        ((float4*)s_in)[tx] = __ldg(src + tx);
        if (tx < 128) ((float4*)s_in)[256 + tx] = __ldg(src + 256 + tx);
    }
    __syncthreads();

    int base = blockIdx.x * 512;
    int vox0 = base + tx;
    int vox1 = vox0 + 256;

    int b = base / DHW;                       // whole block in one batch
    int w0 = vox0 % WW;  int t0 = vox0 / WW;  int h0 = t0 % HH;  int d0 = (t0 / HH) % DD;
    int w1 = vox1 % WW;  int t1i = vox1 / WW; int h1 = t1i % HH; int d1 = (t1i / HH) % DD;

    const uint4* v2 = t2p + (size_t)b * DHW;
    const uint4* v1 = t1p + (size_t)b * DHW;

    float sx0 = s_in[tx * 3 + 0], sy0 = s_in[tx * 3 + 1], sz0 = s_in[tx * 3 + 2];
    float sx1 = s_in[(256 + tx) * 3 + 0], sy1 = s_in[(256 + tx) * 3 + 1],
          sz1 = s_in[(256 + tx) * 3 + 2];

    // ---- phase 1: gather t2 for both voxels (8 independent LDG.128) ----
    Coord ca = make_coord((float)d0 + sx0, (float)h0 + sy0, (float)w0 + sz0);
    Coord cb = make_coord((float)d1 + sx1, (float)h1 + sy1, (float)w1 + sz1);

    uint4 a00 = __ldg(v2 + ca.r00), a01 = __ldg(v2 + ca.r01);
    uint4 a10 = __ldg(v2 + ca.r10), a11 = __ldg(v2 + ca.r11);
    uint4 b00 = __ldg(v2 + cb.r00), b01 = __ldg(v2 + cb.r01);
    uint4 b10 = __ldg(v2 + cb.r10), b11 = __ldg(v2 + cb.r11);

    f3 g2a = reduce_trilerp(ca, a00, a01, a10, a11);
    f3 g2b = reduce_trilerp(cb, b00, b01, b10, b11);

    float cx0 = sx0 + g2a.x, cy0 = sy0 + g2a.y, cz0 = sz0 + g2a.z;
    float cx1 = sx1 + g2b.x, cy1 = sy1 + g2b.y, cz1 = sz1 + g2b.z;

    // ---- phase 2: gather t1 for both voxels ----
    Coord da = make_coord((float)d0 + cx0, (float)h0 + cy0, (float)w0 + cz0);
    Coord db = make_coord((float)d1 + cx1, (float)h1 + cy1, (float)w1 + cz1);

    uint4 c00 = __ldg(v1 + da.r00), c01 = __ldg(v1 + da.r01);
    uint4 c10 = __ldg(v1 + da.r10), c11 = __ldg(v1 + da.r11);
    uint4 d00 = __ldg(v1 + db.r00), d01 = __ldg(v1 + db.r01);
    uint4 d10 = __ldg(v1 + db.r10), d11 = __ldg(v1 + db.r11);

    f3 g1a = reduce_trilerp(da, c00, c01, c10, c11);
    f3 g1b = reduce_trilerp(db, d00, d01, d10, d11);

    s_out[tx * 3 + 0] = cx0 + g1a.x;
    s_out[tx * 3 + 1] = cy0 + g1a.y;
    s_out[tx * 3 + 2] = cz0 + g1a.z;
    s_out[(256 + tx) * 3 + 0] = cx1 + g1b.x;
    s_out[(256 + tx) * 3 + 1] = cy1 + g1b.y;
    s_out[(256 + tx) * 3 + 2] = cz1 + g1b.z;
    __syncthreads();

    {   // write 384 float4
        float4* dst = outv + (size_t)blockIdx.x * 384;
        dst[tx] = ((float4*)s_out)[tx];
        if (tx < 128) dst[256 + tx] = ((float4*)s_out)[256 + tx];
    }
}

extern "C" void kernel_launch(void* const* d_in, const int* in_sizes, int n_in,
                              void* d_out, int out_size) {
    const float* t1 = (const float*)d_in[0];
    const float* t2 = (const float*)d_in[1];
    const float* t3 = (const float*)d_in[2];
    float* out = (float*)d_out;

    uint4 *t1p, *t2p;
    cudaGetSymbolAddress((void**)&t1p, g_t1p);
    cudaGetSymbolAddress((void**)&t2p, g_t2p);

    dim3 qgrid(TOTAL / 1024, 2);
    pairquant2_kernel<<<qgrid, 256>>>((const float4*)t1, (const float4*)t2,
                                      t1p, t2p);

    int blocks = TOTAL / 512;     // 15360
    compose2s_kernel<<<blocks, 256>>>((const float4*)t3, t1p, t2p, (float4*)out);
}